// round 1
// baseline (speedup 1.0000x reference)
#include <cuda_runtime.h>

// Problem constants (fixed by the reference)
#define N_ROWS   131072
#define C_DIM    64
#define K_MAIN   4096
#define K_RES    4096
#define TILE_K   128
#define THREADS  256

// Output layout: [quantized N*C][idx N][residual_quantized N*C][idx_r N]
#define OFF_Q     ((size_t)0)
#define OFF_IDX   ((size_t)N_ROWS * C_DIM)
#define OFF_RQ    ((size_t)N_ROWS * C_DIM + N_ROWS)
#define OFF_IDXR  ((size_t)2 * N_ROWS * C_DIM + N_ROWS)

// Scratch: squared norms of both codebooks (static device arrays; no allocation)
__device__ float g_csq[K_MAIN];
__device__ float g_rsq[K_RES];

__global__ void csq_kernel(const float* __restrict__ cb,
                           const float* __restrict__ rcb) {
    int k = blockIdx.x * blockDim.x + threadIdx.x;
    if (k < K_MAIN) {
        const float4* p = (const float4*)(cb + (size_t)k * C_DIM);
        float s = 0.f;
#pragma unroll
        for (int i = 0; i < C_DIM / 4; i++) {
            float4 v = p[i];
            s += v.x * v.x + v.y * v.y + v.z * v.z + v.w * v.w;
        }
        g_csq[k] = s;
    }
    if (k < K_RES) {
        const float4* p = (const float4*)(rcb + (size_t)k * C_DIM);
        float s = 0.f;
#pragma unroll
        for (int i = 0; i < C_DIM / 4; i++) {
            float4 v = p[i];
            s += v.x * v.x + v.y * v.y + v.z * v.z + v.w * v.w;
        }
        g_rsq[k] = s;
    }
}

// Scan one full codebook (K entries) against the register-resident vector xr.
// s_code / s_sq are shared-memory staging buffers. Tie-break: ascending k,
// strict <, matching jnp.argmin (first minimum wins).
__device__ __forceinline__ void nearest_scan(
    const float xr[C_DIM],
    const float* __restrict__ cb,
    const float* __restrict__ sq,
    float* s_code, float* s_sq,
    int K, float& best, int& bidx)
{
    for (int t = 0; t < K; t += TILE_K) {
        __syncthreads();  // previous tile fully consumed
        // Stage TILE_K codebook rows (coalesced float4 copies)
        {
            const float4* g4 = (const float4*)(cb + (size_t)t * C_DIM);
            float4* s4 = (float4*)s_code;
            const int n4 = TILE_K * C_DIM / 4;  // 2048
#pragma unroll
            for (int i = 0; i < n4 / THREADS; i++)
                s4[threadIdx.x + i * THREADS] = g4[threadIdx.x + i * THREADS];
            if (threadIdx.x < TILE_K)
                s_sq[threadIdx.x] = sq[t + threadIdx.x];
        }
        __syncthreads();

#pragma unroll 2
        for (int k = 0; k < TILE_K; k++) {
            const float4* cp = (const float4*)(s_code + k * C_DIM);
            float a0 = 0.f, a1 = 0.f, a2 = 0.f, a3 = 0.f;
#pragma unroll
            for (int j = 0; j < C_DIM / 4; j++) {
                float4 v = cp[j];  // broadcast: all lanes read same address
                a0 = fmaf(v.x, xr[4 * j + 0], a0);
                a1 = fmaf(v.y, xr[4 * j + 1], a1);
                a2 = fmaf(v.z, xr[4 * j + 2], a2);
                a3 = fmaf(v.w, xr[4 * j + 3], a3);
            }
            float dot = (a0 + a1) + (a2 + a3);
            float score = s_sq[k] - 2.0f * dot;  // ||c||^2 - 2 x.c  (x^2 const per row)
            if (score < best) { best = score; bidx = t + k; }
        }
    }
    __syncthreads();
}

__global__ __launch_bounds__(THREADS)
void rq_kernel(const float* __restrict__ x,
               const float* __restrict__ cb,
               const float* __restrict__ rcb,
               float* __restrict__ out)
{
    __shared__ float s_code[TILE_K * C_DIM];  // 32 KB
    __shared__ float s_sq[TILE_K];

    const int row = blockIdx.x * THREADS + threadIdx.x;  // N divisible, no bounds

    // Load x row into registers
    float xr[C_DIM];
    {
        const float4* xp = (const float4*)(x + (size_t)row * C_DIM);
#pragma unroll
        for (int j = 0; j < C_DIM / 4; j++) {
            float4 v = xp[j];
            xr[4 * j + 0] = v.x; xr[4 * j + 1] = v.y;
            xr[4 * j + 2] = v.z; xr[4 * j + 3] = v.w;
        }
    }

    // ---- Stage 1: main codebook ----
    float best = 3.402823466e38f;
    int bidx = 0;
    nearest_scan(xr, cb, g_csq, s_code, s_sq, K_MAIN, best, bidx);

    // Gather quantized row, emit it, form residual in registers
    {
        const float4* qp = (const float4*)(cb + (size_t)bidx * C_DIM);
        float4* oq = (float4*)(out + OFF_Q + (size_t)row * C_DIM);
#pragma unroll
        for (int j = 0; j < C_DIM / 4; j++) {
            float4 q = qp[j];
            oq[j] = q;
            xr[4 * j + 0] -= q.x; xr[4 * j + 1] -= q.y;
            xr[4 * j + 2] -= q.z; xr[4 * j + 3] -= q.w;
        }
        out[OFF_IDX + row] = (float)bidx;
    }

    // ---- Stage 2: residual codebook on the residual ----
    best = 3.402823466e38f;
    bidx = 0;
    nearest_scan(xr, rcb, g_rsq, s_code, s_sq, K_RES, best, bidx);

    {
        const float4* qp = (const float4*)(rcb + (size_t)bidx * C_DIM);
        float4* oq = (float4*)(out + OFF_RQ + (size_t)row * C_DIM);
#pragma unroll
        for (int j = 0; j < C_DIM / 4; j++)
            oq[j] = qp[j];
        out[OFF_IDXR + row] = (float)bidx;
    }
}

extern "C" void kernel_launch(void* const* d_in, const int* in_sizes, int n_in,
                              void* d_out, int out_size) {
    const float* x   = (const float*)d_in[0];
    const float* cb  = (const float*)d_in[1];
    const float* rcb = (const float*)d_in[2];
    float* out = (float*)d_out;

    csq_kernel<<<K_MAIN / 256, 256>>>(cb, rcb);
    rq_kernel<<<N_ROWS / THREADS, THREADS>>>(x, cb, rcb, out);
}

// round 2
// speedup vs baseline: 1.3923x; 1.3923x over previous
#include <cuda_runtime.h>

// Problem constants (fixed by the reference)
#define N_ROWS   131072
#define C_DIM    64
#define K_CODES  4096
#define M_TILE   64      // rows per block
#define N_TILE   128     // codes per tile
#define THREADS  256

// Output layout: [quantized N*C][idx N][residual_quantized N*C][idx_r N]
#define OFF_Q     ((size_t)0)
#define OFF_IDX   ((size_t)N_ROWS * C_DIM)
#define OFF_RQ    ((size_t)N_ROWS * C_DIM + N_ROWS)
#define OFF_IDXR  ((size_t)2 * N_ROWS * C_DIM + N_ROWS)

// Static device scratch: transposed codebooks [c][n] + squared norms
__device__ float g_cbT[C_DIM * K_CODES];
__device__ float g_rcbT[C_DIM * K_CODES];
__device__ float g_csq[K_CODES];
__device__ float g_rsq[K_CODES];

typedef unsigned long long ull;

__device__ __forceinline__ ull fma2(ull a, ull b, ull c) {
    ull d;
    asm("fma.rn.f32x2 %0, %1, %2, %3;" : "=l"(d) : "l"(a), "l"(b), "l"(c));
    return d;
}
__device__ __forceinline__ float lo32(ull v) { return __uint_as_float((unsigned)v); }
__device__ __forceinline__ float hi32(ull v) { return __uint_as_float((unsigned)(v >> 32)); }

// ---- Pre-kernel: transpose both codebooks + squared norms ----
__global__ void prep_kernel(const float* __restrict__ cb,
                            const float* __restrict__ rcb) {
    int n = blockIdx.x * blockDim.x + threadIdx.x;
    if (n >= K_CODES) return;
    float s = 0.f;
#pragma unroll 8
    for (int c = 0; c < C_DIM; c++) {
        float v = cb[(size_t)n * C_DIM + c];
        g_cbT[(size_t)c * K_CODES + n] = v;   // coalesced across lanes
        s = fmaf(v, v, s);
    }
    g_csq[n] = s;
    s = 0.f;
#pragma unroll 8
    for (int c = 0; c < C_DIM; c++) {
        float v = rcb[(size_t)n * C_DIM + c];
        g_rcbT[(size_t)c * K_CODES + n] = v;
        s = fmaf(v, v, s);
    }
    g_rsq[n] = s;
}

// SMEM partition (dynamic): x_dup [64][128], c_s [64][128], s_csq [128]
#define SMEM_FLOATS (C_DIM * 2 * M_TILE + C_DIM * N_TILE + N_TILE)

__global__ __launch_bounds__(THREADS, 2)
void rq2_kernel(const float* __restrict__ x,
                const float* __restrict__ cb,
                const float* __restrict__ rcb,
                float* __restrict__ out)
{
    extern __shared__ float smem[];
    float* x_dup = smem;                         // [k][2m] duplicated rows, 8192 f
    float* c_s   = smem + C_DIM * 2 * M_TILE;    // [k][n], 8192 f
    float* s_csq = c_s + C_DIM * N_TILE;         // [128]

    const int tid  = threadIdx.x;
    const int tx   = tid & 31;    // code group: 4 codes at tx*4
    const int ty   = tid >> 5;    // row group: 8 rows at ty*8
    const int row0 = blockIdx.x * M_TILE;

    // ---- Build x_dup (transposed + duplicated) ----
    for (int f = tid; f < M_TILE * (C_DIM / 4); f += THREADS) {
        int r  = f >> 4;           // local row 0..63
        int c4 = f & 15;           // float4 index along C
        float4 v = *(const float4*)(x + (size_t)(row0 + r) * C_DIM + c4 * 4);
        float va[4] = {v.x, v.y, v.z, v.w};
#pragma unroll
        for (int e = 0; e < 4; e++) {
            int c = c4 * 4 + e;
            x_dup[c * (2 * M_TILE) + 2 * r]     = va[e];
            x_dup[c * (2 * M_TILE) + 2 * r + 1] = va[e];
        }
    }

    for (int stage = 0; stage < 2; stage++) {
        const float* cbT = stage ? g_rcbT : g_cbT;
        const float* sq  = stage ? g_rsq  : g_csq;
        const float* cbraw = stage ? rcb : cb;

        float best[8];
        int   bidx[8];
#pragma unroll
        for (int i = 0; i < 8; i++) { best[i] = 3.402823466e38f; bidx[i] = 0; }

        for (int tile = 0; tile < K_CODES / N_TILE; tile++) {
            const int n0 = tile * N_TILE;
            __syncthreads();   // previous tile consumed / x_dup ready
            // Load code tile (transposed source -> coalesced, conflict-free)
            for (int f = tid; f < C_DIM * (N_TILE / 4); f += THREADS) {
                int k = f >> 5;        // 0..63
                int p = f & 31;        // float4 along n
                *(float4*)(c_s + k * N_TILE + p * 4) =
                    *(const float4*)(cbT + (size_t)k * K_CODES + n0 + p * 4);
            }
            if (tid < N_TILE) s_csq[tid] = sq[n0 + tid];
            __syncthreads();

            ull acc[16];
#pragma unroll
            for (int i = 0; i < 16; i++) acc[i] = 0ull;

#pragma unroll 16
            for (int k = 0; k < C_DIM; k++) {
                const ulonglong2* ap =
                    (const ulonglong2*)(x_dup + k * (2 * M_TILE) + ty * 16);
                ulonglong2 A0 = ap[0], A1 = ap[1], A2 = ap[2], A3 = ap[3];
                ulonglong2 B = *(const ulonglong2*)(c_s + k * N_TILE + tx * 4);
                acc[0]  = fma2(A0.x, B.x, acc[0]);   acc[1]  = fma2(A0.x, B.y, acc[1]);
                acc[2]  = fma2(A0.y, B.x, acc[2]);   acc[3]  = fma2(A0.y, B.y, acc[3]);
                acc[4]  = fma2(A1.x, B.x, acc[4]);   acc[5]  = fma2(A1.x, B.y, acc[5]);
                acc[6]  = fma2(A1.y, B.x, acc[6]);   acc[7]  = fma2(A1.y, B.y, acc[7]);
                acc[8]  = fma2(A2.x, B.x, acc[8]);   acc[9]  = fma2(A2.x, B.y, acc[9]);
                acc[10] = fma2(A2.y, B.x, acc[10]);  acc[11] = fma2(A2.y, B.y, acc[11]);
                acc[12] = fma2(A3.x, B.x, acc[12]);  acc[13] = fma2(A3.x, B.y, acc[13]);
                acc[14] = fma2(A3.y, B.x, acc[14]);  acc[15] = fma2(A3.y, B.y, acc[15]);
            }

            // Epilogue: scores + running argmin (ascending code order -> strict <)
            const int nb = n0 + tx * 4;
#pragma unroll
            for (int j = 0; j < 2; j++) {
                float cA = s_csq[tx * 4 + 2 * j];
                float cB = s_csq[tx * 4 + 2 * j + 1];
#pragma unroll
                for (int i = 0; i < 8; i++) {
                    ull v = acc[i * 2 + j];
                    float s0 = fmaf(-2.f, lo32(v), cA);
                    float s1 = fmaf(-2.f, hi32(v), cB);
                    if (s0 < best[i]) { best[i] = s0; bidx[i] = nb + 2 * j; }
                    if (s1 < best[i]) { best[i] = s1; bidx[i] = nb + 2 * j + 1; }
                }
            }
        }

        // ---- Cross-lane reduction over tx (32 lanes share the same 8 rows) ----
        int red_idx[8];
#pragma unroll
        for (int i = 0; i < 8; i++) {
            float s = best[i];
            int   b = bidx[i];
#pragma unroll
            for (int off = 16; off > 0; off >>= 1) {
                float so = __shfl_xor_sync(0xffffffffu, s, off);
                int   bo = __shfl_xor_sync(0xffffffffu, b, off);
                if (so < s || (so == s && bo < b)) { s = so; b = bo; }
            }
            red_idx[i] = b;
        }

        // ---- Emit outputs; on stage 0, rewrite x_dup with residuals ----
        {
            const int lane = tx;
            const int m    = lane >> 2;        // 0..7
            const int part = lane & 3;         // 16 floats each
            const int mloc = ty * 8 + m;       // local row
            const int rowg = row0 + mloc;
            const int code = red_idx[m];
            const float4* q4 = (const float4*)(cbraw + (size_t)code * C_DIM + part * 16);
            const size_t obase = (stage ? OFF_RQ : OFF_Q) + (size_t)rowg * C_DIM + part * 16;
#pragma unroll
            for (int jj = 0; jj < 4; jj++) {
                float4 q = q4[jj];
                *(float4*)(out + obase + jj * 4) = q;
                if (stage == 0) {
                    float qa[4] = {q.x, q.y, q.z, q.w};
#pragma unroll
                    for (int e = 0; e < 4; e++) {
                        int c = part * 16 + jj * 4 + e;
                        float r = x_dup[c * (2 * M_TILE) + 2 * mloc] - qa[e];
                        x_dup[c * (2 * M_TILE) + 2 * mloc]     = r;
                        x_dup[c * (2 * M_TILE) + 2 * mloc + 1] = r;
                    }
                }
            }
            if (part == 0)
                out[(stage ? OFF_IDXR : OFF_IDX) + rowg] = (float)code;
        }
        // No explicit sync needed: each warp only reads/writes its own x_dup rows,
        // and c_s reuse is guarded by the tile-loop __syncthreads().
    }
}

extern "C" void kernel_launch(void* const* d_in, const int* in_sizes, int n_in,
                              void* d_out, int out_size) {
    const float* x   = (const float*)d_in[0];
    const float* cb  = (const float*)d_in[1];
    const float* rcb = (const float*)d_in[2];
    float* out = (float*)d_out;

    static int smem_set = 0;
    if (!smem_set) {
        cudaFuncSetAttribute(rq2_kernel,
                             cudaFuncAttributeMaxDynamicSharedMemorySize,
                             SMEM_FLOATS * sizeof(float));
        smem_set = 1;
    }

    prep_kernel<<<K_CODES / 256, 256>>>(cb, rcb);
    rq2_kernel<<<N_ROWS / M_TILE, THREADS, SMEM_FLOATS * sizeof(float)>>>(x, cb, rcb, out);
}

// round 3
// speedup vs baseline: 1.8645x; 1.3391x over previous
#include <cuda_runtime.h>

#define N_ROWS   131072
#define C_DIM    64
#define K_CODES  4096
#define M_TILE   128
#define N_TILE   128
#define THREADS  256
#define XT_PITCH 132          // padded x_T row (words)

// Output layout: [quantized N*C][idx N][residual_quantized N*C][idx_r N]
#define OFF_Q     ((size_t)0)
#define OFF_IDX   ((size_t)N_ROWS * C_DIM)
#define OFF_RQ    ((size_t)N_ROWS * C_DIM + N_ROWS)
#define OFF_IDXR  ((size_t)2 * N_ROWS * C_DIM + N_ROWS)

// Static device scratch: transposed, (-2)-scaled codebooks + squared norms
__device__ float g_cbT[C_DIM * K_CODES];
__device__ float g_rcbT[C_DIM * K_CODES];
__device__ float g_csq[K_CODES];
__device__ float g_rsq[K_CODES];

typedef unsigned long long ull;

__device__ __forceinline__ ull fma2(ull a, ull b, ull c) {
    ull d;
    asm("fma.rn.f32x2 %0, %1, %2, %3;" : "=l"(d) : "l"(a), "l"(b), "l"(c));
    return d;
}
__device__ __forceinline__ float lo32(ull v) { return __uint_as_float((unsigned)v); }
__device__ __forceinline__ float hi32(ull v) { return __uint_as_float((unsigned)(v >> 32)); }
__device__ __forceinline__ ull dup_lo(ull v) {
    ull d; unsigned lo = (unsigned)v;
    asm("mov.b64 %0, {%1, %1};" : "=l"(d) : "r"(lo));
    return d;
}
__device__ __forceinline__ ull dup_hi(ull v) {
    ull d; unsigned hi = (unsigned)(v >> 32);
    asm("mov.b64 %0, {%1, %1};" : "=l"(d) : "r"(hi));
    return d;
}

// ---- Pre-kernel: transpose + scale by -2, plus squared norms ----
__global__ void prep_kernel(const float* __restrict__ cb,
                            const float* __restrict__ rcb) {
    int n = blockIdx.x * blockDim.x + threadIdx.x;
    if (n >= K_CODES) return;
    float s = 0.f;
#pragma unroll 8
    for (int c = 0; c < C_DIM; c++) {
        float v = cb[(size_t)n * C_DIM + c];
        g_cbT[(size_t)c * K_CODES + n] = -2.0f * v;
        s = fmaf(v, v, s);
    }
    g_csq[n] = s;
    s = 0.f;
#pragma unroll 8
    for (int c = 0; c < C_DIM; c++) {
        float v = rcb[(size_t)n * C_DIM + c];
        g_rcbT[(size_t)c * K_CODES + n] = -2.0f * v;
        s = fmaf(v, v, s);
    }
    g_rsq[n] = s;
}

#define SMEM_FLOATS (C_DIM * XT_PITCH + 2 * C_DIM * N_TILE)  // 8448 + 16384

__device__ __forceinline__ void issue_tile(float* c_s, int buf,
                                           const float* __restrict__ src,
                                           int n0, int tid) {
    unsigned base = (unsigned)__cvta_generic_to_shared(c_s + buf * (C_DIM * N_TILE));
#pragma unroll
    for (int o = 0; o < 8; o++) {
        int id = tid + o * THREADS;
        int k  = id >> 5;
        int ch = id & 31;
        const float* s = src + (size_t)k * K_CODES + n0 + ch * 4;
        unsigned d = base + (unsigned)((k * N_TILE + ch * 4) * 4);
        asm volatile("cp.async.cg.shared.global [%0], [%1], 16;"
                     :: "r"(d), "l"(s) : "memory");
    }
    asm volatile("cp.async.commit_group;" ::: "memory");
}

__device__ __forceinline__ void finalize_stage(
    int stage, int row0, int txc, int tyr,
    float* x_T, const float* __restrict__ cbraw, float* __restrict__ out,
    float best[8], int bidx[8])
{
#pragma unroll
    for (int rr = 0; rr < 8; rr++) {
        float s = best[rr];
        int   b = bidx[rr];
#pragma unroll
        for (int off = 1; off < 16; off <<= 1) {
            float so = __shfl_xor_sync(0xffffffffu, s, off);
            int   bo = __shfl_xor_sync(0xffffffffu, b, off);
            if (so < s || (so == s && bo < b)) { s = so; b = bo; }
        }
        const int code = b;
        const int r    = tyr * 8 + rr;
        const int grow = row0 + r;
        const float4 q = *(const float4*)(cbraw + (size_t)code * C_DIM + txc * 4);
        *(float4*)(out + (stage ? OFF_RQ : OFF_Q) + (size_t)grow * C_DIM + txc * 4) = q;
        if (stage == 0) {
            const int d0 = txc * 4;
            x_T[(d0 + 0) * XT_PITCH + r] -= q.x;
            x_T[(d0 + 1) * XT_PITCH + r] -= q.y;
            x_T[(d0 + 2) * XT_PITCH + r] -= q.z;
            x_T[(d0 + 3) * XT_PITCH + r] -= q.w;
        }
        if (txc == 0)
            out[(stage ? OFF_IDXR : OFF_IDX) + grow] = (float)code;
        best[rr] = 3.402823466e38f;
        bidx[rr] = 0;
    }
}

__global__ __launch_bounds__(THREADS, 2)
void rq3_kernel(const float* __restrict__ x,
                const float* __restrict__ cb,
                const float* __restrict__ rcb,
                float* __restrict__ out)
{
    extern __shared__ float smem[];
    float* x_T = smem;                       // [64][132]
    float* c_s = smem + C_DIM * XT_PITCH;    // [2][64][128]

    const int tid  = threadIdx.x;
    const int txc  = tid & 15;   // code group: 8 codes at txc*8
    const int tyr  = tid >> 4;   // row group: 8 rows at tyr*8
    const int row0 = blockIdx.x * M_TILE;

    // ---- Build transposed x tile (un-duplicated) ----
    for (int f = tid; f < M_TILE * (C_DIM / 4); f += THREADS) {
        int r  = f >> 4;
        int c4 = f & 15;
        float4 v = *(const float4*)(x + (size_t)(row0 + r) * C_DIM + c4 * 4);
        x_T[(c4 * 4 + 0) * XT_PITCH + r] = v.x;
        x_T[(c4 * 4 + 1) * XT_PITCH + r] = v.y;
        x_T[(c4 * 4 + 2) * XT_PITCH + r] = v.z;
        x_T[(c4 * 4 + 3) * XT_PITCH + r] = v.w;
    }

    float best[8];
    int   bidx[8];
#pragma unroll
    for (int i = 0; i < 8; i++) { best[i] = 3.402823466e38f; bidx[i] = 0; }

    issue_tile(c_s, 0, g_cbT, 0, tid);

    for (int tt = 0; tt < 64; tt++) {
        if (tt < 63) {
            const int u = tt + 1;
            issue_tile(c_s, u & 1, (u >> 5) ? g_rcbT : g_cbT, (u & 31) * N_TILE, tid);
            asm volatile("cp.async.wait_group 1;" ::: "memory");
        } else {
            asm volatile("cp.async.wait_group 0;" ::: "memory");
        }
        __syncthreads();

        if (tt == 32) {  // stage-0 done: emit outputs, build residuals in x_T
            finalize_stage(0, row0, txc, tyr, x_T, cb, out, best, bidx);
            __syncthreads();
        }

        const int stage = tt >> 5;
        const int n0    = (tt & 31) * N_TILE;
        const float* sqg = (stage ? g_rsq : g_csq) + n0 + txc * 8;
        const float4 cq0 = *(const float4*)(sqg);
        const float4 cq1 = *(const float4*)(sqg + 4);
        const float  cqa[8] = {cq0.x, cq0.y, cq0.z, cq0.w,
                               cq1.x, cq1.y, cq1.z, cq1.w};
        const float* csb = c_s + (tt & 1) * (C_DIM * N_TILE);

        ull acc[8][4];
#pragma unroll
        for (int j = 0; j < 8; j++)
#pragma unroll
            for (int i = 0; i < 4; i++) acc[j][i] = 0ull;

#pragma unroll 8
        for (int k = 0; k < C_DIM; k++) {
            const float* xk = x_T + k * XT_PITCH + tyr * 8;
            ulonglong2 a01 = *(const ulonglong2*)(xk);
            ulonglong2 a23 = *(const ulonglong2*)(xk + 4);
            const float* bk = csb + k * N_TILE + txc * 8;
            ulonglong2 b01 = *(const ulonglong2*)(bk);
            ulonglong2 b23 = *(const ulonglong2*)(bk + 4);
            ull A[4] = {a01.x, a01.y, a23.x, a23.y};   // row pairs (2i, 2i+1)
            ull bd[8] = {dup_lo(b01.x), dup_hi(b01.x),
                         dup_lo(b01.y), dup_hi(b01.y),
                         dup_lo(b23.x), dup_hi(b23.x),
                         dup_lo(b23.y), dup_hi(b23.y)};
#pragma unroll
            for (int j = 0; j < 8; j++)
#pragma unroll
                for (int i = 0; i < 4; i++)
                    acc[j][i] = fma2(A[i], bd[j], acc[j][i]);
        }

        // Epilogue: score = csq + (-2 x.c), running argmin (ascending codes)
#pragma unroll
        for (int j = 0; j < 8; j++) {
            const float cq   = cqa[j];
            const int   code = n0 + txc * 8 + j;
#pragma unroll
            for (int i = 0; i < 4; i++) {
                ull v = acc[j][i];
                float s0 = cq + lo32(v);
                float s1 = cq + hi32(v);
                if (s0 < best[2 * i])     { best[2 * i]     = s0; bidx[2 * i]     = code; }
                if (s1 < best[2 * i + 1]) { best[2 * i + 1] = s1; bidx[2 * i + 1] = code; }
            }
        }
        __syncthreads();
    }

    finalize_stage(1, row0, txc, tyr, x_T, rcb, out, best, bidx);
}

extern "C" void kernel_launch(void* const* d_in, const int* in_sizes, int n_in,
                              void* d_out, int out_size) {
    const float* x   = (const float*)d_in[0];
    const float* cb  = (const float*)d_in[1];
    const float* rcb = (const float*)d_in[2];
    float* out = (float*)d_out;

    static int smem_set = 0;
    if (!smem_set) {
        cudaFuncSetAttribute(rq3_kernel,
                             cudaFuncAttributeMaxDynamicSharedMemorySize,
                             SMEM_FLOATS * sizeof(float));
        smem_set = 1;
    }

    prep_kernel<<<K_CODES / 256, 256>>>(cb, rcb);
    rq3_kernel<<<N_ROWS / M_TILE, THREADS, SMEM_FLOATS * sizeof(float)>>>(x, cb, rcb, out);
}